// round 2
// baseline (speedup 1.0000x reference)
#include <cuda_runtime.h>
#include <math.h>

#define BATCH 2
#define TLEN  2048
#define EMB   1024
#define NHEAD 16
#define HDIM  64
#define MROWS (BATCH*TLEN)   /* 4096 */
#define HID   (4*EMB)        /* 4096 */

// ---- scratch (device globals; no allocation allowed) ----
__device__ float g_h1 [(size_t)MROWS * EMB];        // LN1 out, then attention out (reused)
__device__ float g_qkv[(size_t)MROWS * 3 * EMB];    // QKV
__device__ float g_x1 [(size_t)MROWS * EMB];        // x + attn
__device__ float g_h2 [(size_t)MROWS * EMB];        // LN2 out
__device__ float g_fc [(size_t)MROWS * HID];        // relu(fc)

// ------------------------------------------------------------------
// LayerNorm: one block (256 thr) per row of 1024, one float4/thread
// ------------------------------------------------------------------
__global__ __launch_bounds__(256) void ln_kernel(
    const float* __restrict__ x, const float* __restrict__ scale,
    const float* __restrict__ shift, float* __restrict__ out)
{
    int row = blockIdx.x;
    int t = threadIdx.x;
    const float4* xr = (const float4*)(x + (size_t)row * EMB);
    float4 v = xr[t];
    float s  = v.x + v.y + v.z + v.w;
    float sq = v.x*v.x + v.y*v.y + v.z*v.z + v.w*v.w;

    __shared__ float red[16];
    __shared__ float mv[2];
    #pragma unroll
    for (int o = 16; o > 0; o >>= 1) {
        s  += __shfl_xor_sync(0xffffffffu, s,  o);
        sq += __shfl_xor_sync(0xffffffffu, sq, o);
    }
    if ((t & 31) == 0) { red[t >> 5] = s; red[8 + (t >> 5)] = sq; }
    __syncthreads();
    if (t == 0) {
        float S = 0.f, SQ = 0.f;
        #pragma unroll
        for (int i = 0; i < 8; i++) { S += red[i]; SQ += red[8 + i]; }
        float mean = S * (1.0f / EMB);
        float var  = SQ * (1.0f / EMB) - mean * mean;
        mv[0] = mean; mv[1] = rsqrtf(var + 1e-5f);
    }
    __syncthreads();
    float mean = mv[0], inv = mv[1];
    float4 sc = ((const float4*)scale)[t];
    float4 sh = ((const float4*)shift)[t];
    float4 o4;
    o4.x = (v.x - mean) * inv * sc.x + sh.x;
    o4.y = (v.y - mean) * inv * sc.y + sh.y;
    o4.z = (v.z - mean) * inv * sc.z + sh.z;
    o4.w = (v.w - mean) * inv * sc.w + sh.w;
    ((float4*)(out + (size_t)row * EMB))[t] = o4;
}

// ------------------------------------------------------------------
// Elementwise add: c = a + b  (MROWS*EMB floats)
// ------------------------------------------------------------------
__global__ __launch_bounds__(256) void add_kernel(
    const float4* __restrict__ a, const float4* __restrict__ b, float4* __restrict__ c)
{
    int n = MROWS * EMB / 4;
    for (int i = blockIdx.x * blockDim.x + threadIdx.x; i < n; i += gridDim.x * blockDim.x) {
        float4 u = a[i], v = b[i];
        c[i] = make_float4(u.x + v.x, u.y + v.y, u.z + v.z, u.w + v.w);
    }
}

// ------------------------------------------------------------------
// fp32 SGEMM: C[M,N] = A[M,K] @ B[K,N] + bias (+relu) (+res)
// 64x64 tile, BK=16, 256 threads, 4x4 microtile
// ------------------------------------------------------------------
template<bool RELU, bool HASRES>
__global__ __launch_bounds__(256) void sgemm64(
    const float* __restrict__ A, const float* __restrict__ Bm,
    const float* __restrict__ bias, const float* __restrict__ res,
    float* __restrict__ C, int Mn, int Nn, int Kn)
{
    __shared__ float As[16][64];
    __shared__ float Bs[16][64];
    int tid = threadIdx.x;
    int tx = tid & 15, ty = tid >> 4;
    int m0 = blockIdx.y * 64, n0 = blockIdx.x * 64;
    int ar = tid >> 2, ac = (tid & 3) * 4;     // A tile: row 0..63, k-col {0,4,8,12}
    int br = tid >> 4, bc = (tid & 15) * 4;    // B tile: k-row 0..15, col {0..60}

    const float* Ap = A  + (size_t)(m0 + ar) * Kn + ac;
    const float* Bp = Bm + (size_t)br * Nn + n0 + bc;

    float acc[4][4] = {};
    for (int k0 = 0; k0 < Kn; k0 += 16) {
        float4 a4 = *(const float4*)(Ap + k0);
        As[ac + 0][ar] = a4.x; As[ac + 1][ar] = a4.y;
        As[ac + 2][ar] = a4.z; As[ac + 3][ar] = a4.w;
        float4 b4 = *(const float4*)(Bp + (size_t)k0 * Nn);
        *(float4*)&Bs[br][bc] = b4;
        __syncthreads();
        #pragma unroll
        for (int kk = 0; kk < 16; kk++) {
            float a[4], bb[4];
            *(float4*)a  = *(const float4*)&As[kk][ty * 4];
            *(float4*)bb = *(const float4*)&Bs[kk][tx * 4];
            #pragma unroll
            for (int i = 0; i < 4; i++)
                #pragma unroll
                for (int j = 0; j < 4; j++)
                    acc[i][j] += a[i] * bb[j];
        }
        __syncthreads();
    }
    #pragma unroll
    for (int i = 0; i < 4; i++) {
        int m = m0 + ty * 4 + i;
        #pragma unroll
        for (int j = 0; j < 4; j++) {
            int n = n0 + tx * 4 + j;
            float c = acc[i][j] + bias[n];
            if (RELU)   c = fmaxf(c, 0.f);
            if (HASRES) c += res[(size_t)m * Nn + n];
            C[(size_t)m * Nn + n] = c;
        }
    }
}

// ------------------------------------------------------------------
// Flash attention (causal), fp32. One block per (b, h, 64-row q tile).
// 256 threads (16x16), 4x4 microtiles, online softmax.
// qkv layout: row = b*TLEN + t, cols: [q | k | v], head h at offset h*64.
// ------------------------------------------------------------------
__global__ __launch_bounds__(256) void attn_kernel(
    const float* __restrict__ qkv, float* __restrict__ out)
{
    extern __shared__ float smd[];
    const int LD = 65;                 // pad to break bank conflicts
    float* Qs = smd;
    float* Ks = Qs + 64 * LD;
    float* Vs = Ks + 64 * LD;
    float* Ps = Vs + 64 * LD;

    int b = blockIdx.y >> 4, h = blockIdx.y & 15;
    int qt = blockIdx.x;
    int q0 = qt * 64;
    int tid = threadIdx.x;
    int tx = tid & 15, ty = tid >> 4;

    const float* qb = qkv + (size_t)b * TLEN * (3 * EMB) + h * HDIM;
    const float* kb = qb + EMB;
    const float* vb = qb + 2 * EMB;

    // load Q tile (64 x 64)
    for (int i = tid; i < 64 * 16; i += 256) {
        int r = i >> 4, c = (i & 15) * 4;
        const float* p = qb + (size_t)(q0 + r) * (3 * EMB) + c;
        Qs[r * LD + c + 0] = p[0]; Qs[r * LD + c + 1] = p[1];
        Qs[r * LD + c + 2] = p[2]; Qs[r * LD + c + 3] = p[3];
    }

    float m_i[4], l_i[4], o[4][4];
    #pragma unroll
    for (int i = 0; i < 4; i++) {
        m_i[i] = -1e30f; l_i[i] = 0.f;
        #pragma unroll
        for (int j = 0; j < 4; j++) o[i][j] = 0.f;
    }

    for (int kt = 0; kt <= qt; kt++) {
        int k0 = kt * 64;
        __syncthreads();   // prior PV done (and Q load on first iter)
        for (int i = tid; i < 64 * 16; i += 256) {
            int r = i >> 4, c = (i & 15) * 4;
            const float* pk = kb + (size_t)(k0 + r) * (3 * EMB) + c;
            Ks[r * LD + c + 0] = pk[0]; Ks[r * LD + c + 1] = pk[1];
            Ks[r * LD + c + 2] = pk[2]; Ks[r * LD + c + 3] = pk[3];
            const float* pv = vb + (size_t)(k0 + r) * (3 * EMB) + c;
            Vs[r * LD + c + 0] = pv[0]; Vs[r * LD + c + 1] = pv[1];
            Vs[r * LD + c + 2] = pv[2]; Vs[r * LD + c + 3] = pv[3];
        }
        __syncthreads();

        // S = Q K^T * 1/8  (4x4 per thread)
        float s[4][4] = {};
        #pragma unroll 8
        for (int dd = 0; dd < 64; dd++) {
            float qa[4], ka[4];
            #pragma unroll
            for (int i = 0; i < 4; i++) qa[i] = Qs[(ty * 4 + i) * LD + dd];
            #pragma unroll
            for (int j = 0; j < 4; j++) ka[j] = Ks[(tx * 4 + j) * LD + dd];
            #pragma unroll
            for (int i = 0; i < 4; i++)
                #pragma unroll
                for (int j = 0; j < 4; j++)
                    s[i][j] += qa[i] * ka[j];
        }
        bool diag = (kt == qt);
        #pragma unroll
        for (int i = 0; i < 4; i++) {
            int qi = q0 + ty * 4 + i;
            #pragma unroll
            for (int j = 0; j < 4; j++) {
                s[i][j] *= 0.125f;
                if (diag && (k0 + tx * 4 + j > qi)) s[i][j] = -1e30f;
            }
        }

        // online softmax per row
        #pragma unroll
        for (int i = 0; i < 4; i++) {
            float mx = fmaxf(fmaxf(s[i][0], s[i][1]), fmaxf(s[i][2], s[i][3]));
            mx = fmaxf(mx, __shfl_xor_sync(0xffffffffu, mx, 1));
            mx = fmaxf(mx, __shfl_xor_sync(0xffffffffu, mx, 2));
            mx = fmaxf(mx, __shfl_xor_sync(0xffffffffu, mx, 4));
            mx = fmaxf(mx, __shfl_xor_sync(0xffffffffu, mx, 8));
            float mn = fmaxf(m_i[i], mx);
            float alpha = __expf(m_i[i] - mn);
            float rs = 0.f;
            #pragma unroll
            for (int j = 0; j < 4; j++) { s[i][j] = __expf(s[i][j] - mn); rs += s[i][j]; }
            rs += __shfl_xor_sync(0xffffffffu, rs, 1);
            rs += __shfl_xor_sync(0xffffffffu, rs, 2);
            rs += __shfl_xor_sync(0xffffffffu, rs, 4);
            rs += __shfl_xor_sync(0xffffffffu, rs, 8);
            l_i[i] = l_i[i] * alpha + rs;
            m_i[i] = mn;
            #pragma unroll
            for (int j = 0; j < 4; j++) o[i][j] *= alpha;
            #pragma unroll
            for (int j = 0; j < 4; j++) Ps[(ty * 4 + i) * LD + tx * 4 + j] = s[i][j];
        }
        __syncthreads();

        // O += P @ V
        #pragma unroll 8
        for (int kk = 0; kk < 64; kk++) {
            float pa[4], va[4];
            #pragma unroll
            for (int i = 0; i < 4; i++) pa[i] = Ps[(ty * 4 + i) * LD + kk];
            #pragma unroll
            for (int j = 0; j < 4; j++) va[j] = Vs[kk * LD + tx * 4 + j];
            #pragma unroll
            for (int i = 0; i < 4; i++)
                #pragma unroll
                for (int j = 0; j < 4; j++)
                    o[i][j] += pa[i] * va[j];
        }
    }

    #pragma unroll
    for (int i = 0; i < 4; i++) {
        float inv = 1.f / l_i[i];
        int row = b * TLEN + q0 + ty * 4 + i;
        float* po = out + (size_t)row * EMB + h * HDIM + tx * 4;
        #pragma unroll
        for (int j = 0; j < 4; j++) po[j] = o[i][j] * inv;
    }
}

// ------------------------------------------------------------------
extern "C" void kernel_launch(void* const* d_in, const int* in_sizes, int n_in,
                              void* d_out, int out_size)
{
    const float* x      = (const float*)d_in[0];
    const float* ln1s   = (const float*)d_in[1];
    const float* ln1b   = (const float*)d_in[2];
    const float* w_qkv  = (const float*)d_in[3];
    const float* b_qkv  = (const float*)d_in[4];
    const float* ln2s   = (const float*)d_in[5];
    const float* ln2b   = (const float*)d_in[6];
    const float* w_fc   = (const float*)d_in[7];
    const float* b_fc   = (const float*)d_in[8];
    const float* w_proj = (const float*)d_in[9];
    const float* b_proj = (const float*)d_in[10];
    float* out = (float*)d_out;

    float *h1, *qkv, *x1, *h2, *fc;
    cudaGetSymbolAddress((void**)&h1,  g_h1);
    cudaGetSymbolAddress((void**)&qkv, g_qkv);
    cudaGetSymbolAddress((void**)&x1,  g_x1);
    cudaGetSymbolAddress((void**)&h2,  g_h2);
    cudaGetSymbolAddress((void**)&fc,  g_fc);

    const int attn_smem = 4 * 64 * 65 * (int)sizeof(float);  // 66560 B
    cudaFuncSetAttribute(attn_kernel, cudaFuncAttributeMaxDynamicSharedMemorySize, attn_smem);

    // 1. h1 = LN1(x)
    ln_kernel<<<MROWS, 256>>>(x, ln1s, ln1b, h1);
    // 2. qkv = h1 @ w_qkv + b_qkv
    sgemm64<false, false><<<dim3(3 * EMB / 64, MROWS / 64), 256>>>(
        h1, w_qkv, b_qkv, nullptr, qkv, MROWS, 3 * EMB, EMB);
    // 3. attention -> h1 (reuse)
    attn_kernel<<<dim3(TLEN / 64, BATCH * NHEAD), 256, attn_smem>>>(qkv, h1);
    // 4. x1 = x + attn
    add_kernel<<<1024, 256>>>((const float4*)x, (const float4*)h1, (float4*)x1);
    // 5. h2 = LN2(x1)
    ln_kernel<<<MROWS, 256>>>(x1, ln2s, ln2b, h2);
    // 6. fc = relu(h2 @ w_fc + b_fc)
    sgemm64<true, false><<<dim3(HID / 64, MROWS / 64), 256>>>(
        h2, w_fc, b_fc, nullptr, fc, MROWS, HID, EMB);
    // 7. out = x1 + fc @ w_proj + b_proj
    sgemm64<false, true><<<dim3(EMB / 64, MROWS / 64), 256>>>(
        fc, w_proj, b_proj, x1, out, MROWS, EMB, HID);
}

// round 4
// speedup vs baseline: 1.8108x; 1.8108x over previous
#include <cuda_runtime.h>
#include <cuda_bf16.h>
#include <math.h>
#include <stdint.h>

#define BATCH 2
#define TLEN  2048
#define EMB   1024
#define NHEAD 16
#define HDIM  64
#define MROWS (BATCH*TLEN)   /* 4096 */
#define HID   (4*EMB)        /* 4096 */

typedef __nv_bfloat16 bf16;

// ---- scratch (device globals; no allocation allowed) ----
__device__ float g_h1 [(size_t)MROWS * EMB];
__device__ float g_qkv[(size_t)MROWS * 3 * EMB];
__device__ float g_x1 [(size_t)MROWS * EMB];
__device__ float g_h2 [(size_t)MROWS * EMB];
__device__ float g_fc [(size_t)MROWS * HID];
__device__ bf16  g_a3 [(size_t)MROWS * 3 * HID];    // split activations [M, 3K]
__device__ bf16  g_w3 [(size_t)12582912];           // split weights [N, 3K]

__device__ __forceinline__ uint32_t smem_u32(const void* p) {
    uint32_t a;
    asm("{ .reg .u64 t; cvta.to.shared.u64 t, %1; cvt.u32.u64 %0, t; }" : "=r"(a) : "l"(p));
    return a;
}
__device__ __forceinline__ void cp16(uint32_t saddr, const void* gaddr) {
    asm volatile("cp.async.cg.shared.global [%0], [%1], 16;" :: "r"(saddr), "l"(gaddr) : "memory");
}
__device__ __forceinline__ void ldsm_x4(uint32_t* r, uint32_t addr) {
    asm volatile("ldmatrix.sync.aligned.m8n8.x4.shared.b16 {%0,%1,%2,%3}, [%4];"
                 : "=r"(r[0]), "=r"(r[1]), "=r"(r[2]), "=r"(r[3]) : "r"(addr));
}
__device__ __forceinline__ void mma16816(float* c, const uint32_t* a, uint32_t b0, uint32_t b1) {
    asm volatile(
        "mma.sync.aligned.m16n8k16.row.col.f32.bf16.bf16.f32 "
        "{%0,%1,%2,%3}, {%4,%5,%6,%7}, {%8,%9}, {%0,%1,%2,%3};"
        : "+f"(c[0]), "+f"(c[1]), "+f"(c[2]), "+f"(c[3])
        : "r"(a[0]), "r"(a[1]), "r"(a[2]), "r"(a[3]), "r"(b0), "r"(b1));
}

// ------------------------------------------------------------------
// Split-precision conversion (triple-K bf16 trick)
//   activations: A[M,K] f32 -> [M,3K] bf16 as [hi, hi, lo]
//   weights:     W[K,N] f32 -> [N,3K] bf16 as [hi, lo, hi] (transposed)
// Dot over 3K gives ah*bh + ah*bl + al*bh (drops only al*bl ~ 2^-18)
// ------------------------------------------------------------------
__global__ __launch_bounds__(256) void convert_act(
    const float* __restrict__ A, bf16* __restrict__ out, int M, int K)
{
    int i = blockIdx.x * blockDim.x + threadIdx.x;
    if (i >= M * K) return;
    int r = i / K, k = i % K;
    float a = A[i];
    bf16 hi = __float2bfloat16(a);
    bf16 lo = __float2bfloat16(a - __bfloat162float(hi));
    size_t o = (size_t)r * 3 * K + 3 * (size_t)k;
    out[o] = hi; out[o + 1] = hi; out[o + 2] = lo;
}

__global__ __launch_bounds__(1024) void convert_wt(
    const float* __restrict__ W, bf16* __restrict__ out, int K, int N)
{
    __shared__ float t[32][33];
    int tx = threadIdx.x, ty = threadIdx.y;
    int k0 = blockIdx.x * 32, n0 = blockIdx.y * 32;
    t[ty][tx] = W[(size_t)(k0 + ty) * N + n0 + tx];
    __syncthreads();
    float w = t[tx][ty];               // k = k0+tx, n = n0+ty
    bf16 hi = __float2bfloat16(w);
    bf16 lo = __float2bfloat16(w - __bfloat162float(hi));
    size_t o = (size_t)(n0 + ty) * 3 * K + 3 * (size_t)(k0 + tx);
    out[o] = hi; out[o + 1] = lo; out[o + 2] = hi;
}

// ------------------------------------------------------------------
// HMMA GEMM: C[M,N] = A3[M,K3] . B3[N,K3]^T + bias (+relu) (+res)
// BM=128 BN=128 BK=32, 4-stage cp.async, 8 warps (2x4), mma.m16n8k16 bf16.
// SMEM rows: 32 bf16 = 64B data, 80B stride (conflict-free ldmatrix).
// ------------------------------------------------------------------
#define ROWB   80
#define TILEB  (128*ROWB)      /* 10240 */
#define STAGEB (2*TILEB)       /* 20480 */
#define NSTAGE 4
#define GSMEM  (NSTAGE*STAGEB) /* 81920 */

template<bool RELU, bool HASRES>
__global__ __launch_bounds__(256, 2)
void gemm_tc(const bf16* __restrict__ A3, const bf16* __restrict__ B3,
             const float* __restrict__ bias, const float* __restrict__ res,
             float* __restrict__ C, int N, int K3)
{
    extern __shared__ __align__(128) unsigned char smem[];
    uint32_t sb = smem_u32(smem);
    int tid = threadIdx.x, w = tid >> 5, l = tid & 31;
    int wm = w >> 2, wn = w & 3;
    int m0 = blockIdx.y * 128, n0 = blockIdx.x * 128;
    int NCH = K3 >> 5;

    const bf16* Ab = A3 + (size_t)m0 * K3;
    const bf16* Bb = B3 + (size_t)n0 * K3;

    // loader geometry: 512 16B-chunks per tile, 2 per thread per tile
    int r0c = tid >> 1;              // not used; explicit below
    (void)r0c;
    int lrow[2], lch[2];
    #pragma unroll
    for (int i = 0; i < 2; i++) {
        int idx = tid + i * 256;
        lrow[i] = idx >> 2; lch[i] = idx & 3;
    }

    // fragment base addresses (per-lane)
    uint32_t aBase = sb + (uint32_t)((wm * 64 + ((l >> 3) & 1) * 8 + (l & 7)) * ROWB + (l >> 4) * 16);
    uint32_t bBase = sb + TILEB + (uint32_t)((wn * 32 + (l >> 4) * 8 + (l & 7)) * ROWB + ((l >> 3) & 1) * 16);

    float acc[4][4][4];
    #pragma unroll
    for (int i = 0; i < 4; i++)
        #pragma unroll
        for (int j = 0; j < 4; j++)
            #pragma unroll
            for (int q = 0; q < 4; q++) acc[i][j][q] = 0.f;

    // prologue: stages 0..2
    #pragma unroll
    for (int s = 0; s < NSTAGE - 1; s++) {
        size_t kc = (size_t)s * 32;
        #pragma unroll
        for (int i = 0; i < 2; i++) {
            uint32_t so = (uint32_t)(s * STAGEB + lrow[i] * ROWB + lch[i] * 16);
            cp16(sb + so,         Ab + (size_t)lrow[i] * K3 + kc + lch[i] * 8);
            cp16(sb + TILEB + so, Bb + (size_t)lrow[i] * K3 + kc + lch[i] * 8);
        }
        asm volatile("cp.async.commit_group;" ::: "memory");
    }

    for (int c = 0; c < NCH; c++) {
        int nc = c + NSTAGE - 1;
        if (nc < NCH) {
            int buf = nc & 3;
            size_t kc = (size_t)nc * 32;
            #pragma unroll
            for (int i = 0; i < 2; i++) {
                uint32_t so = (uint32_t)(buf * STAGEB + lrow[i] * ROWB + lch[i] * 16);
                cp16(sb + so,         Ab + (size_t)lrow[i] * K3 + kc + lch[i] * 8);
                cp16(sb + TILEB + so, Bb + (size_t)lrow[i] * K3 + kc + lch[i] * 8);
            }
        }
        asm volatile("cp.async.commit_group;" ::: "memory");
        asm volatile("cp.async.wait_group 3;" ::: "memory");
        __syncthreads();

        uint32_t as0 = aBase + (uint32_t)((c & 3) * STAGEB);
        uint32_t bs0 = bBase + (uint32_t)((c & 3) * STAGEB);
        #pragma unroll
        for (int ks = 0; ks < 2; ks++) {
            uint32_t ar[4][4], br[2][4];
            #pragma unroll
            for (int mt = 0; mt < 4; mt++)
                ldsm_x4(ar[mt], as0 + mt * (16 * ROWB) + ks * 32);
            #pragma unroll
            for (int p = 0; p < 2; p++)
                ldsm_x4(br[p], bs0 + p * (16 * ROWB) + ks * 32);
            #pragma unroll
            for (int mt = 0; mt < 4; mt++) {
                #pragma unroll
                for (int nt = 0; nt < 4; nt++) {
                    int p = nt >> 1, hh = (nt & 1) * 2;
                    mma16816(acc[mt][nt], ar[mt], br[p][hh], br[p][hh + 1]);
                }
            }
        }
        __syncthreads();
    }

    // epilogue
    int g = l >> 2, t4 = l & 3;
    #pragma unroll
    for (int mt = 0; mt < 4; mt++) {
        int row0 = m0 + wm * 64 + mt * 16 + g;
        #pragma unroll
        for (int nt = 0; nt < 4; nt++) {
            int col = n0 + wn * 32 + nt * 8 + t4 * 2;
            float2 bv = *(const float2*)(bias + col);
            float v0 = acc[mt][nt][0] + bv.x;
            float v1 = acc[mt][nt][1] + bv.y;
            float v2 = acc[mt][nt][2] + bv.x;
            float v3 = acc[mt][nt][3] + bv.y;
            if (RELU) {
                v0 = fmaxf(v0, 0.f); v1 = fmaxf(v1, 0.f);
                v2 = fmaxf(v2, 0.f); v3 = fmaxf(v3, 0.f);
            }
            if (HASRES) {
                float2 r1 = *(const float2*)(res + (size_t)row0 * N + col);
                float2 r2 = *(const float2*)(res + (size_t)(row0 + 8) * N + col);
                v0 += r1.x; v1 += r1.y; v2 += r2.x; v3 += r2.y;
            }
            *(float2*)(C + (size_t)row0 * N + col)       = make_float2(v0, v1);
            *(float2*)(C + (size_t)(row0 + 8) * N + col) = make_float2(v2, v3);
        }
    }
}

// ------------------------------------------------------------------
// LayerNorm: one block (256 thr) per row of 1024, one float4/thread
// ------------------------------------------------------------------
__global__ __launch_bounds__(256) void ln_kernel(
    const float* __restrict__ x, const float* __restrict__ scale,
    const float* __restrict__ shift, float* __restrict__ out)
{
    int row = blockIdx.x;
    int t = threadIdx.x;
    const float4* xr = (const float4*)(x + (size_t)row * EMB);
    float4 v = xr[t];
    float s  = v.x + v.y + v.z + v.w;
    float sq = v.x*v.x + v.y*v.y + v.z*v.z + v.w*v.w;

    __shared__ float red[16];
    __shared__ float mv[2];
    #pragma unroll
    for (int o = 16; o > 0; o >>= 1) {
        s  += __shfl_xor_sync(0xffffffffu, s,  o);
        sq += __shfl_xor_sync(0xffffffffu, sq, o);
    }
    if ((t & 31) == 0) { red[t >> 5] = s; red[8 + (t >> 5)] = sq; }
    __syncthreads();
    if (t == 0) {
        float S = 0.f, SQ = 0.f;
        #pragma unroll
        for (int i = 0; i < 8; i++) { S += red[i]; SQ += red[8 + i]; }
        float mean = S * (1.0f / EMB);
        float var  = SQ * (1.0f / EMB) - mean * mean;
        mv[0] = mean; mv[1] = rsqrtf(var + 1e-5f);
    }
    __syncthreads();
    float mean = mv[0], inv = mv[1];
    float4 sc = ((const float4*)scale)[t];
    float4 sh = ((const float4*)shift)[t];
    float4 o4;
    o4.x = (v.x - mean) * inv * sc.x + sh.x;
    o4.y = (v.y - mean) * inv * sc.y + sh.y;
    o4.z = (v.z - mean) * inv * sc.z + sh.z;
    o4.w = (v.w - mean) * inv * sc.w + sh.w;
    ((float4*)(out + (size_t)row * EMB))[t] = o4;
}

// ------------------------------------------------------------------
__global__ __launch_bounds__(256) void add_kernel(
    const float4* __restrict__ a, const float4* __restrict__ b, float4* __restrict__ c)
{
    int n = MROWS * EMB / 4;
    for (int i = blockIdx.x * blockDim.x + threadIdx.x; i < n; i += gridDim.x * blockDim.x) {
        float4 u = a[i], v = b[i];
        c[i] = make_float4(u.x + v.x, u.y + v.y, u.z + v.z, u.w + v.w);
    }
}

// ------------------------------------------------------------------
// Flash attention (causal), fp32 SIMT (unchanged)
// ------------------------------------------------------------------
__global__ __launch_bounds__(256) void attn_kernel(
    const float* __restrict__ qkv, float* __restrict__ out)
{
    extern __shared__ float smd[];
    const int LD = 65;
    float* Qs = smd;
    float* Ks = Qs + 64 * LD;
    float* Vs = Ks + 64 * LD;
    float* Ps = Vs + 64 * LD;

    int b = blockIdx.y >> 4, h = blockIdx.y & 15;
    int qt = blockIdx.x;
    int q0 = qt * 64;
    int tid = threadIdx.x;
    int tx = tid & 15, ty = tid >> 4;

    const float* qb = qkv + (size_t)b * TLEN * (3 * EMB) + h * HDIM;
    const float* kb = qb + EMB;
    const float* vb = qb + 2 * EMB;

    for (int i = tid; i < 64 * 16; i += 256) {
        int r = i >> 4, c = (i & 15) * 4;
        const float* p = qb + (size_t)(q0 + r) * (3 * EMB) + c;
        Qs[r * LD + c + 0] = p[0]; Qs[r * LD + c + 1] = p[1];
        Qs[r * LD + c + 2] = p[2]; Qs[r * LD + c + 3] = p[3];
    }

    float m_i[4], l_i[4], o[4][4];
    #pragma unroll
    for (int i = 0; i < 4; i++) {
        m_i[i] = -1e30f; l_i[i] = 0.f;
        #pragma unroll
        for (int j = 0; j < 4; j++) o[i][j] = 0.f;
    }

    for (int kt = 0; kt <= qt; kt++) {
        int k0 = kt * 64;
        __syncthreads();
        for (int i = tid; i < 64 * 16; i += 256) {
            int r = i >> 4, c = (i & 15) * 4;
            const float* pk = kb + (size_t)(k0 + r) * (3 * EMB) + c;
            Ks[r * LD + c + 0] = pk[0]; Ks[r * LD + c + 1] = pk[1];
            Ks[r * LD + c + 2] = pk[2]; Ks[r * LD + c + 3] = pk[3];
            const float* pv = vb + (size_t)(k0 + r) * (3 * EMB) + c;
            Vs[r * LD + c + 0] = pv[0]; Vs[r * LD + c + 1] = pv[1];
            Vs[r * LD + c + 2] = pv[2]; Vs[r * LD + c + 3] = pv[3];
        }
        __syncthreads();

        float s[4][4] = {};
        #pragma unroll 8
        for (int dd = 0; dd < 64; dd++) {
            float qa[4], ka[4];
            #pragma unroll
            for (int i = 0; i < 4; i++) qa[i] = Qs[(ty * 4 + i) * LD + dd];
            #pragma unroll
            for (int j = 0; j < 4; j++) ka[j] = Ks[(tx * 4 + j) * LD + dd];
            #pragma unroll
            for (int i = 0; i < 4; i++)
                #pragma unroll
                for (int j = 0; j < 4; j++)
                    s[i][j] += qa[i] * ka[j];
        }
        bool diag = (kt == qt);
        #pragma unroll
        for (int i = 0; i < 4; i++) {
            int qi = q0 + ty * 4 + i;
            #pragma unroll
            for (int j = 0; j < 4; j++) {
                s[i][j] *= 0.125f;
                if (diag && (k0 + tx * 4 + j > qi)) s[i][j] = -1e30f;
            }
        }

        #pragma unroll
        for (int i = 0; i < 4; i++) {
            float mx = fmaxf(fmaxf(s[i][0], s[i][1]), fmaxf(s[i][2], s[i][3]));
            mx = fmaxf(mx, __shfl_xor_sync(0xffffffffu, mx, 1));
            mx = fmaxf(mx, __shfl_xor_sync(0xffffffffu, mx, 2));
            mx = fmaxf(mx, __shfl_xor_sync(0xffffffffu, mx, 4));
            mx = fmaxf(mx, __shfl_xor_sync(0xffffffffu, mx, 8));
            float mn = fmaxf(m_i[i], mx);
            float alpha = __expf(m_i[i] - mn);
            float rs = 0.f;
            #pragma unroll
            for (int j = 0; j < 4; j++) { s[i][j] = __expf(s[i][j] - mn); rs += s[i][j]; }
            rs += __shfl_xor_sync(0xffffffffu, rs, 1);
            rs += __shfl_xor_sync(0xffffffffu, rs, 2);
            rs += __shfl_xor_sync(0xffffffffu, rs, 4);
            rs += __shfl_xor_sync(0xffffffffu, rs, 8);
            l_i[i] = l_i[i] * alpha + rs;
            m_i[i] = mn;
            #pragma unroll
            for (int j = 0; j < 4; j++) o[i][j] *= alpha;
            #pragma unroll
            for (int j = 0; j < 4; j++) Ps[(ty * 4 + i) * LD + tx * 4 + j] = s[i][j];
        }
        __syncthreads();

        #pragma unroll 8
        for (int kk = 0; kk < 64; kk++) {
            float pa[4], va[4];
            #pragma unroll
            for (int i = 0; i < 4; i++) pa[i] = Ps[(ty * 4 + i) * LD + kk];
            #pragma unroll
            for (int j = 0; j < 4; j++) va[j] = Vs[kk * LD + tx * 4 + j];
            #pragma unroll
            for (int i = 0; i < 4; i++)
                #pragma unroll
                for (int j = 0; j < 4; j++)
                    o[i][j] += pa[i] * va[j];
        }
    }

    #pragma unroll
    for (int i = 0; i < 4; i++) {
        float inv = 1.f / l_i[i];
        int row = b * TLEN + q0 + ty * 4 + i;
        float* po = out + (size_t)row * EMB + h * HDIM + tx * 4;
        #pragma unroll
        for (int j = 0; j < 4; j++) po[j] = o[i][j] * inv;
    }
}

// ------------------------------------------------------------------
extern "C" void kernel_launch(void* const* d_in, const int* in_sizes, int n_in,
                              void* d_out, int out_size)
{
    const float* x      = (const float*)d_in[0];
    const float* ln1s   = (const float*)d_in[1];
    const float* ln1b   = (const float*)d_in[2];
    const float* w_qkv  = (const float*)d_in[3];
    const float* b_qkv  = (const float*)d_in[4];
    const float* ln2s   = (const float*)d_in[5];
    const float* ln2b   = (const float*)d_in[6];
    const float* w_fc   = (const float*)d_in[7];
    const float* b_fc   = (const float*)d_in[8];
    const float* w_proj = (const float*)d_in[9];
    const float* b_proj = (const float*)d_in[10];
    float* out = (float*)d_out;

    float *h1, *qkv, *x1, *h2, *fc;
    bf16 *a3, *w3;
    cudaGetSymbolAddress((void**)&h1,  g_h1);
    cudaGetSymbolAddress((void**)&qkv, g_qkv);
    cudaGetSymbolAddress((void**)&x1,  g_x1);
    cudaGetSymbolAddress((void**)&h2,  g_h2);
    cudaGetSymbolAddress((void**)&fc,  g_fc);
    cudaGetSymbolAddress((void**)&a3,  g_a3);
    cudaGetSymbolAddress((void**)&w3,  g_w3);

    const int attn_smem = 4 * 64 * 65 * (int)sizeof(float);  // 66560 B
    cudaFuncSetAttribute(attn_kernel, cudaFuncAttributeMaxDynamicSharedMemorySize, attn_smem);
    cudaFuncSetAttribute(gemm_tc<false,false>, cudaFuncAttributeMaxDynamicSharedMemorySize, GSMEM);
    cudaFuncSetAttribute(gemm_tc<true,false>,  cudaFuncAttributeMaxDynamicSharedMemorySize, GSMEM);
    cudaFuncSetAttribute(gemm_tc<false,true>,  cudaFuncAttributeMaxDynamicSharedMemorySize, GSMEM);

    // 1. h1 = LN1(x)
    ln_kernel<<<MROWS, 256>>>(x, ln1s, ln1b, h1);
    // 2. qkv = h1 @ w_qkv + b_qkv   (HMMA, triple-K bf16)
    convert_act<<<(MROWS * EMB + 255) / 256, 256>>>(h1, a3, MROWS, EMB);
    convert_wt<<<dim3(EMB / 32, 3 * EMB / 32), dim3(32, 32)>>>(w_qkv, w3, EMB, 3 * EMB);
    gemm_tc<false,false><<<dim3(3 * EMB / 128, MROWS / 128), 256, GSMEM>>>(
        a3, w3, b_qkv, nullptr, qkv, 3 * EMB, 3 * EMB);
    // 3. attention -> h1 (reuse)
    attn_kernel<<<dim3(TLEN / 64, BATCH * NHEAD), 256, attn_smem>>>(qkv, h1);
    // 4. x1 = x + attn
    add_kernel<<<1024, 256>>>((const float4*)x, (const float4*)h1, (float4*)x1);
    // 5. h2 = LN2(x1)
    ln_kernel<<<MROWS, 256>>>(x1, ln2s, ln2b, h2);
    // 6. fc = relu(h2 @ w_fc + b_fc)
    convert_act<<<(MROWS * EMB + 255) / 256, 256>>>(h2, a3, MROWS, EMB);
    convert_wt<<<dim3(EMB / 32, HID / 32), dim3(32, 32)>>>(w_fc, w3, EMB, HID);
    gemm_tc<true,false><<<dim3(HID / 128, MROWS / 128), 256, GSMEM>>>(
        a3, w3, b_fc, nullptr, fc, HID, 3 * EMB);
    // 7. out = x1 + fc @ w_proj + b_proj
    convert_act<<<(MROWS * HID + 255) / 256, 256>>>(fc, a3, MROWS, HID);
    convert_wt<<<dim3(HID / 32, EMB / 32), dim3(32, 32)>>>(w_proj, w3, HID, EMB);
    gemm_tc<false,true><<<dim3(EMB / 128, MROWS / 128), 256, GSMEM>>>(
        a3, w3, b_proj, x1, out, EMB, 3 * HID);
}

// round 5
// speedup vs baseline: 2.4248x; 1.3391x over previous
#include <cuda_runtime.h>
#include <cuda_bf16.h>
#include <math.h>
#include <stdint.h>

#define BATCH 2
#define TLEN  2048
#define EMB   1024
#define NHEAD 16
#define HDIM  64
#define MROWS (BATCH*TLEN)   /* 4096 */
#define HID   (4*EMB)        /* 4096 */

typedef __nv_bfloat16 bf16;

// ---- scratch (device globals; no allocation allowed) ----
__device__ float g_qkv[(size_t)MROWS * 3 * EMB];          // qkv fp32
__device__ float g_x1 [(size_t)MROWS * EMB];              // x + attn
__device__ bf16  g_ln3[(size_t)MROWS * 3 * EMB];          // LN split out [M,3K]
__device__ bf16  g_w3 [(size_t)12582912];                 // split weights [N,3K]
__device__ bf16  g_a3 [(size_t)MROWS * 3 * HID];          // fc split out [M,12288]
__device__ bf16  g_q3 [(size_t)32 * TLEN * 192];          // Q split [bh,t,192]
__device__ bf16  g_k3 [(size_t)32 * TLEN * 192];          // K split [bh,t,192]
__device__ bf16  g_v3 [(size_t)32 * HDIM * 3 * TLEN];     // V split-transposed [bh,dv,6144]

__device__ __forceinline__ uint32_t smem_u32(const void* p) {
    uint32_t a;
    asm("{ .reg .u64 t; cvta.to.shared.u64 t, %1; cvt.u32.u64 %0, t; }" : "=r"(a) : "l"(p));
    return a;
}
__device__ __forceinline__ void cp16(uint32_t saddr, const void* gaddr) {
    asm volatile("cp.async.cg.shared.global [%0], [%1], 16;" :: "r"(saddr), "l"(gaddr) : "memory");
}
__device__ __forceinline__ void ldsm_x4(uint32_t* r, uint32_t addr) {
    asm volatile("ldmatrix.sync.aligned.m8n8.x4.shared.b16 {%0,%1,%2,%3}, [%4];"
                 : "=r"(r[0]), "=r"(r[1]), "=r"(r[2]), "=r"(r[3]) : "r"(addr));
}
__device__ __forceinline__ void mma16816(float* c, const uint32_t* a, uint32_t b0, uint32_t b1) {
    asm volatile(
        "mma.sync.aligned.m16n8k16.row.col.f32.bf16.bf16.f32 "
        "{%0,%1,%2,%3}, {%4,%5,%6,%7}, {%8,%9}, {%0,%1,%2,%3};"
        : "+f"(c[0]), "+f"(c[1]), "+f"(c[2]), "+f"(c[3])
        : "r"(a[0]), "r"(a[1]), "r"(a[2]), "r"(a[3]), "r"(b0), "r"(b1));
}
__device__ __forceinline__ uint32_t pk2(bf16 a, bf16 b) {
    return (uint32_t)__bfloat16_as_ushort(a) | ((uint32_t)__bfloat16_as_ushort(b) << 16);
}
__device__ __forceinline__ void split2(float v, bf16& hi, bf16& lo) {
    hi = __float2bfloat16(v);
    lo = __float2bfloat16(v - __bfloat162float(hi));
}

// ------------------------------------------------------------------
// Weight conversion: W[K,N] f32 -> [N,3K] bf16 as (hi, lo, hi)  [B pattern]
// ------------------------------------------------------------------
__global__ __launch_bounds__(1024) void convert_wt(
    const float* __restrict__ W, bf16* __restrict__ out, int K, int N)
{
    __shared__ float t[32][33];
    int tx = threadIdx.x, ty = threadIdx.y;
    int k0 = blockIdx.x * 32, n0 = blockIdx.y * 32;
    t[ty][tx] = W[(size_t)(k0 + ty) * N + n0 + tx];
    __syncthreads();
    float w = t[tx][ty];               // k = k0+tx, n = n0+ty
    bf16 hi, lo; split2(w, hi, lo);
    size_t o = (size_t)(n0 + ty) * 3 * K + 3 * (size_t)(k0 + tx);
    out[o] = hi; out[o + 1] = lo; out[o + 2] = hi;
}

// ------------------------------------------------------------------
// LayerNorm fused with activation split: x row(1024) -> (hi,hi,lo) row(3072)
// ------------------------------------------------------------------
__global__ __launch_bounds__(256) void ln_split(
    const float* __restrict__ x, const float* __restrict__ scale,
    const float* __restrict__ shift, bf16* __restrict__ out3)
{
    int row = blockIdx.x;
    int t = threadIdx.x;
    const float4* xr = (const float4*)(x + (size_t)row * EMB);
    float4 v = xr[t];
    float s  = v.x + v.y + v.z + v.w;
    float sq = v.x*v.x + v.y*v.y + v.z*v.z + v.w*v.w;

    __shared__ float red[16];
    __shared__ float mv[2];
    #pragma unroll
    for (int o = 16; o > 0; o >>= 1) {
        s  += __shfl_xor_sync(0xffffffffu, s,  o);
        sq += __shfl_xor_sync(0xffffffffu, sq, o);
    }
    if ((t & 31) == 0) { red[t >> 5] = s; red[8 + (t >> 5)] = sq; }
    __syncthreads();
    if (t == 0) {
        float S = 0.f, SQ = 0.f;
        #pragma unroll
        for (int i = 0; i < 8; i++) { S += red[i]; SQ += red[8 + i]; }
        float mean = S * (1.0f / EMB);
        float var  = SQ * (1.0f / EMB) - mean * mean;
        mv[0] = mean; mv[1] = rsqrtf(var + 1e-5f);
    }
    __syncthreads();
    float mean = mv[0], inv = mv[1];
    float4 sc = ((const float4*)scale)[t];
    float4 sh = ((const float4*)shift)[t];
    float o0 = (v.x - mean) * inv * sc.x + sh.x;
    float o1 = (v.y - mean) * inv * sc.y + sh.y;
    float o2 = (v.z - mean) * inv * sc.z + sh.z;
    float o3 = (v.w - mean) * inv * sc.w + sh.w;
    bf16 h0,l0,h1,l1,h2,l2,h3,l3;
    split2(o0,h0,l0); split2(o1,h1,l1); split2(o2,h2,l2); split2(o3,h3,l3);
    uint32_t* p = (uint32_t*)(out3 + (size_t)row * 3 * EMB) + 6 * t;
    p[0] = pk2(h0,h0); p[1] = pk2(l0,h1); p[2] = pk2(h1,l1);
    p[3] = pk2(h2,h2); p[4] = pk2(l2,h3); p[5] = pk2(h3,l3);
}

// ------------------------------------------------------------------
// prep_attn: from qkv fp32, build q3 (A pattern), k3 (B), v3t (B, transposed)
// one block per (bh, 64-token tile); 256 thr, thread = (row r = tid/4, 16-col chunk)
// ------------------------------------------------------------------
__global__ __launch_bounds__(256) void prep_attn(
    const float* __restrict__ qkv, bf16* __restrict__ q3,
    bf16* __restrict__ k3, bf16* __restrict__ v3)
{
    __shared__ float vt[64][65];
    int bh = blockIdx.y;
    int tt = blockIdx.x;
    int b = bh >> 4, h = bh & 15;
    int t0 = tt * 64;
    int tid = threadIdx.x;
    int r = tid >> 2, cc = (tid & 3) * 16;
    const float* base = qkv + ((size_t)(b * TLEN + t0 + r)) * 3072 + h * 64;

    // Q: A pattern (hi,hi,lo)
    {
        const float* p = base + cc;
        uint32_t* d = (uint32_t*)(q3 + ((size_t)bh * TLEN + t0 + r) * 192 + 3 * cc);
        #pragma unroll
        for (int j = 0; j < 16; j += 2) {
            bf16 a0,b0,a1,b1;
            split2(p[j], a0, b0); split2(p[j+1], a1, b1);
            d[0] = pk2(a0,a0); d[1] = pk2(b0,a1); d[2] = pk2(a1,b1);
            d += 3;
        }
    }
    // K: B pattern (hi,lo,hi)
    {
        const float* p = base + 1024 + cc;
        uint32_t* d = (uint32_t*)(k3 + ((size_t)bh * TLEN + t0 + r) * 192 + 3 * cc);
        #pragma unroll
        for (int j = 0; j < 16; j += 2) {
            bf16 a0,b0,a1,b1;
            split2(p[j], a0, b0); split2(p[j+1], a1, b1);
            d[0] = pk2(a0,b0); d[1] = pk2(a0,a1); d[2] = pk2(b1,a1);
            d += 3;
        }
    }
    // V transpose to smem
    {
        const float* p = base + 2048 + cc;
        #pragma unroll
        for (int j = 0; j < 16; j++) vt[cc + j][r] = p[j];
    }
    __syncthreads();
    // V out: row dv = r, s chunk cc: B pattern (hi,lo,hi)
    {
        uint32_t* d = (uint32_t*)(v3 + ((size_t)bh * 64 + r) * (3 * TLEN) + (size_t)tt * 192 + 3 * cc);
        #pragma unroll
        for (int j = 0; j < 16; j += 2) {
            bf16 a0,b0,a1,b1;
            split2(vt[r][cc + j], a0, b0); split2(vt[r][cc + j + 1], a1, b1);
            d[0] = pk2(a0,b0); d[1] = pk2(a0,a1); d[2] = pk2(b1,a1);
            d += 3;
        }
    }
}

// ------------------------------------------------------------------
// HMMA GEMM: C[M,N] = A3[M,K3] . B3[N,K3]^T + bias (+relu) (+res | split-out)
// BM=128 BN=128 BK=32, 4-stage cp.async (1 barrier/iter), 8 warps (2x4).
// ------------------------------------------------------------------
#define ROWB   80
#define TILEB  (128*ROWB)
#define STAGEB (2*TILEB)
#define GSMEM  (4*STAGEB)

template<bool RELU, bool HASRES, bool WSPLIT>
__global__ __launch_bounds__(256, 2)
void gemm_tc(const bf16* __restrict__ A3, const bf16* __restrict__ B3,
             const float* __restrict__ bias, const float* __restrict__ res,
             float* __restrict__ C, bf16* __restrict__ C3, int N, int K3)
{
    extern __shared__ __align__(128) unsigned char smem[];
    uint32_t sb = smem_u32(smem);
    int tid = threadIdx.x, w = tid >> 5, l = tid & 31;
    int wm = w >> 2, wn = w & 3;
    int m0 = blockIdx.y * 128, n0 = blockIdx.x * 128;
    int NCH = K3 >> 5;

    const bf16* Ab = A3 + (size_t)m0 * K3;
    const bf16* Bb = B3 + (size_t)n0 * K3;

    int lrow[2], lch[2];
    #pragma unroll
    for (int i = 0; i < 2; i++) {
        int idx = tid + i * 256;
        lrow[i] = idx >> 2; lch[i] = idx & 3;
    }

    uint32_t aBase = sb + (uint32_t)((wm * 64 + ((l >> 3) & 1) * 8 + (l & 7)) * ROWB + (l >> 4) * 16);
    uint32_t bBase = sb + TILEB + (uint32_t)((wn * 32 + (l >> 4) * 8 + (l & 7)) * ROWB + ((l >> 3) & 1) * 16);

    float acc[4][4][4];
    #pragma unroll
    for (int i = 0; i < 4; i++)
        #pragma unroll
        for (int j = 0; j < 4; j++)
            #pragma unroll
            for (int q = 0; q < 4; q++) acc[i][j][q] = 0.f;

    // prologue: stages 0..2
    #pragma unroll
    for (int s = 0; s < 3; s++) {
        size_t kc = (size_t)s * 32;
        #pragma unroll
        for (int i = 0; i < 2; i++) {
            uint32_t so = (uint32_t)(s * STAGEB + lrow[i] * ROWB + lch[i] * 16);
            cp16(sb + so,         Ab + (size_t)lrow[i] * K3 + kc + lch[i] * 8);
            cp16(sb + TILEB + so, Bb + (size_t)lrow[i] * K3 + kc + lch[i] * 8);
        }
        asm volatile("cp.async.commit_group;" ::: "memory");
    }

    for (int c = 0; c < NCH; c++) {
        asm volatile("cp.async.wait_group 2;" ::: "memory");
        __syncthreads();
        int nc = c + 3;
        if (nc < NCH) {
            int buf = nc & 3;
            size_t kc = (size_t)nc * 32;
            #pragma unroll
            for (int i = 0; i < 2; i++) {
                uint32_t so = (uint32_t)(buf * STAGEB + lrow[i] * ROWB + lch[i] * 16);
                cp16(sb + so,         Ab + (size_t)lrow[i] * K3 + kc + lch[i] * 8);
                cp16(sb + TILEB + so, Bb + (size_t)lrow[i] * K3 + kc + lch[i] * 8);
            }
        }
        asm volatile("cp.async.commit_group;" ::: "memory");

        uint32_t as0 = aBase + (uint32_t)((c & 3) * STAGEB);
        uint32_t bs0 = bBase + (uint32_t)((c & 3) * STAGEB);
        #pragma unroll
        for (int ks = 0; ks < 2; ks++) {
            uint32_t ar[4][4], br[2][4];
            #pragma unroll
            for (int mt = 0; mt < 4; mt++)
                ldsm_x4(ar[mt], as0 + mt * (16 * ROWB) + ks * 32);
            #pragma unroll
            for (int p = 0; p < 2; p++)
                ldsm_x4(br[p], bs0 + p * (16 * ROWB) + ks * 32);
            #pragma unroll
            for (int mt = 0; mt < 4; mt++) {
                #pragma unroll
                for (int nt = 0; nt < 4; nt++) {
                    int p = nt >> 1, hh = (nt & 1) * 2;
                    mma16816(acc[mt][nt], ar[mt], br[p][hh], br[p][hh + 1]);
                }
            }
        }
    }

    // epilogue
    int g = l >> 2, t4 = l & 3;
    #pragma unroll
    for (int mt = 0; mt < 4; mt++) {
        int row0 = m0 + wm * 64 + mt * 16 + g;
        #pragma unroll
        for (int nt = 0; nt < 4; nt++) {
            int col = n0 + wn * 32 + nt * 8 + t4 * 2;
            float2 bv = *(const float2*)(bias + col);
            float v0 = acc[mt][nt][0] + bv.x;
            float v1 = acc[mt][nt][1] + bv.y;
            float v2 = acc[mt][nt][2] + bv.x;
            float v3 = acc[mt][nt][3] + bv.y;
            if (RELU) {
                v0 = fmaxf(v0, 0.f); v1 = fmaxf(v1, 0.f);
                v2 = fmaxf(v2, 0.f); v3 = fmaxf(v3, 0.f);
            }
            if (WSPLIT) {
                bf16 h0,l0,h1,l1;
                split2(v0,h0,l0); split2(v1,h1,l1);
                uint32_t* p = (uint32_t*)(C3 + (size_t)row0 * 3 * N + 3 * col);
                p[0] = pk2(h0,h0); p[1] = pk2(l0,h1); p[2] = pk2(h1,l1);
                split2(v2,h0,l0); split2(v3,h1,l1);
                uint32_t* q = (uint32_t*)(C3 + (size_t)(row0 + 8) * 3 * N + 3 * col);
                q[0] = pk2(h0,h0); q[1] = pk2(l0,h1); q[2] = pk2(h1,l1);
            } else {
                if (HASRES) {
                    float2 r1 = *(const float2*)(res + (size_t)row0 * N + col);
                    float2 r2 = *(const float2*)(res + (size_t)(row0 + 8) * N + col);
                    v0 += r1.x; v1 += r1.y; v2 += r2.x; v3 += r2.y;
                }
                *(float2*)(C + (size_t)row0 * N + col)       = make_float2(v0, v1);
                *(float2*)(C + (size_t)(row0 + 8) * N + col) = make_float2(v2, v3);
            }
        }
    }
}

// ------------------------------------------------------------------
// HMMA flash attention (causal) with triple-split bf16.
// Block: (qi reversed, bh). 8 warps x (16 rows x 64 cols). Q tile 128, K tile 64.
// Writes x1 = x + attn (fused residual).
// ------------------------------------------------------------------
#define LDROW 400
#define AQ_OFF   0u
#define AK_OFF   51200u
#define AV_OFF   102400u
#define AP_OFF   153600u
#define ASMEM    204800

__global__ __launch_bounds__(256) void attn_hmma(
    const bf16* __restrict__ q3, const bf16* __restrict__ k3,
    const bf16* __restrict__ v3, const float* __restrict__ x,
    float* __restrict__ x1)
{
    extern __shared__ __align__(128) unsigned char sm[];
    uint32_t sb = smem_u32(sm);
    int tid = threadIdx.x, w = tid >> 5, l = tid & 31;
    int g = l >> 2, t4 = l & 3;
    int bh = blockIdx.y;
    int b = bh >> 4, h = bh & 15;
    int qi = (int)(gridDim.x - 1) - (int)blockIdx.x;   // heavy tiles first
    int q0 = qi * 128;
    int ktn = 2 * qi + 2;

    const bf16* qb = q3 + ((size_t)bh * TLEN + q0) * 192;
    const bf16* kb = k3 + (size_t)bh * TLEN * 192;
    const bf16* vb = v3 + (size_t)bh * 64 * (3 * TLEN);

    // Q tile: 128 rows x 24 chunks
    for (int i = tid; i < 3072; i += 256) {
        int r = i / 24, c = i % 24;
        cp16(sb + AQ_OFF + r * LDROW + c * 16, qb + (size_t)r * 192 + c * 8);
    }
    asm volatile("cp.async.commit_group;" ::: "memory");
    // KV tile 0 into buf 0
    for (int i = tid; i < 1536; i += 256) {
        int r = i / 24, c = i % 24;
        cp16(sb + AK_OFF + r * LDROW + c * 16, kb + (size_t)r * 192 + c * 8);
        cp16(sb + AV_OFF + r * LDROW + c * 16, vb + (size_t)r * (3 * TLEN) + c * 8);
    }
    asm volatile("cp.async.commit_group;" ::: "memory");

    uint32_t rowPartA = (uint32_t)((16 * w + ((l >> 3) & 1) * 8 + (l & 7)) * LDROW + (l >> 4) * 16);
    uint32_t aQ = sb + AQ_OFF + rowPartA;
    uint32_t aP = sb + AP_OFF + rowPartA;
    uint32_t bPart = (uint32_t)(((l >> 4) * 8 + (l & 7)) * LDROW + ((l >> 3) & 1) * 16);

    float m_[2] = {-1e30f, -1e30f};
    float l_[2] = {0.f, 0.f};
    float oacc[8][4];
    #pragma unroll
    for (int nt = 0; nt < 8; nt++)
        #pragma unroll
        for (int q = 0; q < 4; q++) oacc[nt][q] = 0.f;

    for (int kt = 0; kt < ktn; kt++) {
        asm volatile("cp.async.wait_group 0;" ::: "memory");
        __syncthreads();
        // prefetch next KV
        if (kt + 1 < ktn) {
            uint32_t boff = ((kt + 1) & 1) * 25600u;
            for (int i = tid; i < 1536; i += 256) {
                int r = i / 24, c = i % 24;
                cp16(sb + AK_OFF + boff + r * LDROW + c * 16,
                     kb + ((size_t)(kt + 1) * 64 + r) * 192 + c * 8);
                cp16(sb + AV_OFF + boff + r * LDROW + c * 16,
                     vb + (size_t)r * (3 * TLEN) + (size_t)(kt + 1) * 192 + c * 8);
            }
        }
        asm volatile("cp.async.commit_group;" ::: "memory");

        uint32_t boff = (kt & 1) * 25600u;
        uint32_t bK = sb + AK_OFF + boff + bPart;
        uint32_t bV = sb + AV_OFF + boff + bPart;

        // S = Q K^T
        float sacc[8][4];
        #pragma unroll
        for (int nt = 0; nt < 8; nt++)
            #pragma unroll
            for (int q = 0; q < 4; q++) sacc[nt][q] = 0.f;
        #pragma unroll
        for (int ks = 0; ks < 12; ks++) {
            uint32_t ar[4], br[4][4];
            ldsm_x4(ar, aQ + ks * 32);
            #pragma unroll
            for (int p = 0; p < 4; p++)
                ldsm_x4(br[p], bK + p * (16 * LDROW) + ks * 32);
            #pragma unroll
            for (int nt = 0; nt < 8; nt++)
                mma16816(sacc[nt], ar, br[nt >> 1][(nt & 1) * 2], br[nt >> 1][(nt & 1) * 2 + 1]);
        }

        // scale + causal mask
        int k0 = kt * 64;
        if (k0 + 63 > q0) {
            int r0 = q0 + 16 * w + g, r1 = r0 + 8;
            #pragma unroll
            for (int nt = 0; nt < 8; nt++) {
                int c0 = k0 + nt * 8 + t4 * 2;
                sacc[nt][0] = (c0     > r0) ? -1e30f : sacc[nt][0] * 0.125f;
                sacc[nt][1] = (c0 + 1 > r0) ? -1e30f : sacc[nt][1] * 0.125f;
                sacc[nt][2] = (c0     > r1) ? -1e30f : sacc[nt][2] * 0.125f;
                sacc[nt][3] = (c0 + 1 > r1) ? -1e30f : sacc[nt][3] * 0.125f;
            }
        } else {
            #pragma unroll
            for (int nt = 0; nt < 8; nt++)
                #pragma unroll
                for (int q = 0; q < 4; q++) sacc[nt][q] *= 0.125f;
        }

        // online softmax per row-half
        #pragma unroll
        for (int h2 = 0; h2 < 2; h2++) {
            float mx = -1e30f;
            #pragma unroll
            for (int nt = 0; nt < 8; nt++)
                mx = fmaxf(mx, fmaxf(sacc[nt][h2 * 2], sacc[nt][h2 * 2 + 1]));
            mx = fmaxf(mx, __shfl_xor_sync(0xffffffffu, mx, 1));
            mx = fmaxf(mx, __shfl_xor_sync(0xffffffffu, mx, 2));
            float mn = fmaxf(m_[h2], mx);
            float al = __expf(m_[h2] - mn);
            float sum = 0.f;
            #pragma unroll
            for (int nt = 0; nt < 8; nt++) {
                float p0 = __expf(sacc[nt][h2 * 2]     - mn);
                float p1 = __expf(sacc[nt][h2 * 2 + 1] - mn);
                sacc[nt][h2 * 2] = p0; sacc[nt][h2 * 2 + 1] = p1;
                sum += p0 + p1;
            }
            sum += __shfl_xor_sync(0xffffffffu, sum, 1);
            sum += __shfl_xor_sync(0xffffffffu, sum, 2);
            l_[h2] = l_[h2] * al + sum;
            m_[h2] = mn;
            #pragma unroll
            for (int nt = 0; nt < 8; nt++) {
                oacc[nt][h2 * 2]     *= al;
                oacc[nt][h2 * 2 + 1] *= al;
            }
        }
        __syncwarp();

        // write P split (A pattern) rows 16w+g and +8
        {
            unsigned char* prow0 = sm + AP_OFF + (16 * w + g) * LDROW;
            unsigned char* prow1 = prow0 + 8 * LDROW;
            #pragma unroll
            for (int nt = 0; nt < 8; nt++) {
                int sl = nt * 8 + t4 * 2;
                bf16 h0, l0, h1, l1;
                split2(sacc[nt][0], h0, l0); split2(sacc[nt][1], h1, l1);
                uint32_t* p = (uint32_t*)(prow0 + 6 * sl);
                p[0] = pk2(h0, h0); p[1] = pk2(l0, h1); p[2] = pk2(h1, l1);
                split2(sacc[nt][2], h0, l0); split2(sacc[nt][3], h1, l1);
                uint32_t* q = (uint32_t*)(prow1 + 6 * sl);
                q[0] = pk2(h0, h0); q[1] = pk2(l0, h1); q[2] = pk2(h1, l1);
            }
        }
        __syncwarp();

        // O += P V
        #pragma unroll
        for (int ks = 0; ks < 12; ks++) {
            uint32_t ar[4], br[4][4];
            ldsm_x4(ar, aP + ks * 32);
            #pragma unroll
            for (int p = 0; p < 4; p++)
                ldsm_x4(br[p], bV + p * (16 * LDROW) + ks * 32);
            #pragma unroll
            for (int nt = 0; nt < 8; nt++)
                mma16816(oacc[nt], ar, br[nt >> 1][(nt & 1) * 2], br[nt >> 1][(nt & 1) * 2 + 1]);
        }
    }

    // epilogue: y/l + residual x -> x1
    #pragma unroll
    for (int h2 = 0; h2 < 2; h2++) {
        float inv = 1.f / l_[h2];
        int row = b * TLEN + q0 + 16 * w + g + 8 * h2;
        const float* xr = x  + (size_t)row * EMB + h * 64;
        float*       xo = x1 + (size_t)row * EMB + h * 64;
        #pragma unroll
        for (int nt = 0; nt < 8; nt++) {
            int c = nt * 8 + t4 * 2;
            float2 xv = *(const float2*)(xr + c);
            float2 yv;
            yv.x = oacc[nt][h2 * 2]     * inv + xv.x;
            yv.y = oacc[nt][h2 * 2 + 1] * inv + xv.y;
            *(float2*)(xo + c) = yv;
        }
    }
}

// ------------------------------------------------------------------
extern "C" void kernel_launch(void* const* d_in, const int* in_sizes, int n_in,
                              void* d_out, int out_size)
{
    const float* x      = (const float*)d_in[0];
    const float* ln1s   = (const float*)d_in[1];
    const float* ln1b   = (const float*)d_in[2];
    const float* w_qkv  = (const float*)d_in[3];
    const float* b_qkv  = (const float*)d_in[4];
    const float* ln2s   = (const float*)d_in[5];
    const float* ln2b   = (const float*)d_in[6];
    const float* w_fc   = (const float*)d_in[7];
    const float* b_fc   = (const float*)d_in[8];
    const float* w_proj = (const float*)d_in[9];
    const float* b_proj = (const float*)d_in[10];
    float* out = (float*)d_out;

    float *qkv, *x1;
    bf16 *ln3, *w3, *a3, *q3, *k3, *v3;
    cudaGetSymbolAddress((void**)&qkv, g_qkv);
    cudaGetSymbolAddress((void**)&x1,  g_x1);
    cudaGetSymbolAddress((void**)&ln3, g_ln3);
    cudaGetSymbolAddress((void**)&w3,  g_w3);
    cudaGetSymbolAddress((void**)&a3,  g_a3);
    cudaGetSymbolAddress((void**)&q3,  g_q3);
    cudaGetSymbolAddress((void**)&k3,  g_k3);
    cudaGetSymbolAddress((void**)&v3,  g_v3);

    cudaFuncSetAttribute(attn_hmma, cudaFuncAttributeMaxDynamicSharedMemorySize, ASMEM);
    cudaFuncSetAttribute(gemm_tc<false,false,false>, cudaFuncAttributeMaxDynamicSharedMemorySize, GSMEM);
    cudaFuncSetAttribute(gemm_tc<true,false,true>,   cudaFuncAttributeMaxDynamicSharedMemorySize, GSMEM);
    cudaFuncSetAttribute(gemm_tc<false,true,false>,  cudaFuncAttributeMaxDynamicSharedMemorySize, GSMEM);

    // 1. ln3 = split(LN1(x))
    ln_split<<<MROWS, 256>>>(x, ln1s, ln1b, ln3);
    // 2. qkv = ln1 @ w_qkv + b_qkv
    convert_wt<<<dim3(EMB / 32, 3 * EMB / 32), dim3(32, 32)>>>(w_qkv, w3, EMB, 3 * EMB);
    gemm_tc<false,false,false><<<dim3(3 * EMB / 128, MROWS / 128), 256, GSMEM>>>(
        ln3, w3, b_qkv, nullptr, qkv, nullptr, 3 * EMB, 3 * EMB);
    // 3. split/transpose q,k,v
    prep_attn<<<dim3(TLEN / 64, 32), 256>>>(qkv, q3, k3, v3);
    // 4. x1 = x + attention  (fused residual)
    attn_hmma<<<dim3(TLEN / 128, 32), 256, ASMEM>>>(q3, k3, v3, x, x1);
    // 5. ln3 = split(LN2(x1))
    ln_split<<<MROWS, 256>>>(x1, ln2s, ln2b, ln3);
    // 6. a3 = split(relu(ln2 @ w_fc + b_fc))
    convert_wt<<<dim3(EMB / 32, HID / 32), dim3(32, 32)>>>(w_fc, w3, EMB, HID);
    gemm_tc<true,false,true><<<dim3(HID / 128, MROWS / 128), 256, GSMEM>>>(
        ln3, w3, b_fc, nullptr, nullptr, a3, HID, 3 * EMB);
    // 7. out = x1 + fc @ w_proj + b_proj
    convert_wt<<<dim3(HID / 32, EMB / 32), dim3(32, 32)>>>(w_proj, w3, HID, EMB);
    gemm_tc<false,true,false><<<dim3(EMB / 128, MROWS / 128), 256, GSMEM>>>(
        a3, w3, b_proj, x1, out, nullptr, EMB, 3 * HID);
}